// round 12
// baseline (speedup 1.0000x reference)
#include <cuda_runtime.h>
#include <math.h>

// Problem constants (fixed by reference: N_NODES=10000, N_EDGES=160000, H=128, L=16)
#define H      128
#define NMAX   10000
#define LAYERS 16
#define EPSV   1e-5f
#define ET     8   // edges per block
#define NT     8   // nodes per block

// Scratch: per-layer scatter-sum accumulator (no cudaMalloc allowed)
__device__ float g_agg[(size_t)NMAX * H];

__global__ void zero_agg_kernel(int total) {
    int i = blockIdx.x * blockDim.x + threadIdx.x;
    if (i < total) g_agg[i] = 0.0f;
}

// acc[0..7] += w * sp[0..7]  (sp 16B-aligned shared row, broadcast)
__device__ __forceinline__ void fma8(float (&acc)[8], float w, const float* sp) {
    float4 c0 = *reinterpret_cast<const float4*>(sp);
    float4 c1 = *reinterpret_cast<const float4*>(sp + 4);
    acc[0] = fmaf(w, c0.x, acc[0]);
    acc[1] = fmaf(w, c0.y, acc[1]);
    acc[2] = fmaf(w, c0.z, acc[2]);
    acc[3] = fmaf(w, c0.w, acc[3]);
    acc[4] = fmaf(w, c1.x, acc[4]);
    acc[5] = fmaf(w, c1.y, acc[5]);
    acc[6] = fmaf(w, c1.z, acc[6]);
    acc[7] = fmaf(w, c1.w, acc[7]);
}

__device__ __forceinline__ float silu_f(float x) {
    // x * sigmoid(x); __expf fast-path is accurate to ~1e-6 rel, fine vs 1e-3 gate
    return x / (1.0f + __expf(-x));
}

// ---------------------------------------------------------------------------
// Edge update: cat=[ef, nf[src], nf[dst]] (3H) -> Lin+SiLU -> Lin -> LN -> +ef
// Also scatter-adds the new edge feature into g_agg[dst].
// One block = 8 edges, 128 threads (thread j owns output column j).
// ---------------------------------------------------------------------------
__global__ __launch_bounds__(128) void edge_kernel(
    float* __restrict__ ef, const float* __restrict__ nf,
    const int* __restrict__ src, const int* __restrict__ dst,
    const float* __restrict__ W1, const float* __restrict__ b1,   // W1: [3H][H]
    const float* __restrict__ W2, const float* __restrict__ b2,   // W2: [H][H]
    const float* __restrict__ gg, const float* __restrict__ bb)
{
    __shared__ __align__(16) float s_cat[3 * H][ET]; // transposed: [k][edge]
    __shared__ __align__(16) float s_h[H][ET];
    __shared__ float s_red[2][ET][4];

    const int tid = threadIdx.x;
    const int e0  = blockIdx.x * ET;

    int di[ET];
#pragma unroll
    for (int e = 0; e < ET; e++) {
        int ei = e0 + e;
        int si = src[ei];
        di[e]  = dst[ei];
        s_cat[tid][e]         = ef[(size_t)ei * H + tid];
        s_cat[H + tid][e]     = nf[(size_t)si * H + tid];
        s_cat[2 * H + tid][e] = nf[(size_t)di[e] * H + tid];
    }
    __syncthreads();

    // ---- GEMM1 (K=3H) + SiLU ----
    float acc[ET];
    {
        float b = b1[tid];
#pragma unroll
        for (int e = 0; e < ET; e++) acc[e] = b;
    }
    const float* w1p = W1 + tid;  // column j, coalesced across threads
#pragma unroll 4
    for (int k = 0; k < 3 * H; k++) {
        float w = w1p[(size_t)k * H];
        fma8(acc, w, &s_cat[k][0]);
    }
#pragma unroll
    for (int e = 0; e < ET; e++) s_h[tid][e] = silu_f(acc[e]);
    __syncthreads();

    // ---- GEMM2 (K=H) ----
    float acc2[ET];
    {
        float b = b2[tid];
#pragma unroll
        for (int e = 0; e < ET; e++) acc2[e] = b;
    }
    const float* w2p = W2 + tid;
#pragma unroll 4
    for (int k = 0; k < H; k++) {
        float w = w2p[(size_t)k * H];
        fma8(acc2, w, &s_h[k][0]);
    }

    // ---- LayerNorm over the 128 columns (per edge) ----
    float sum[ET], sq[ET];
#pragma unroll
    for (int e = 0; e < ET; e++) { sum[e] = acc2[e]; sq[e] = acc2[e] * acc2[e]; }
#pragma unroll
    for (int off = 16; off > 0; off >>= 1) {
#pragma unroll
        for (int e = 0; e < ET; e++) {
            sum[e] += __shfl_xor_sync(0xffffffffu, sum[e], off);
            sq[e]  += __shfl_xor_sync(0xffffffffu, sq[e],  off);
        }
    }
    const int warp = tid >> 5;
    if ((tid & 31) == 0) {
#pragma unroll
        for (int e = 0; e < ET; e++) { s_red[0][e][warp] = sum[e]; s_red[1][e][warp] = sq[e]; }
    }
    __syncthreads();

    const float gj = gg[tid], bj = bb[tid];
#pragma unroll
    for (int e = 0; e < ET; e++) {
        float s   = s_red[0][e][0] + s_red[0][e][1] + s_red[0][e][2] + s_red[0][e][3];
        float ss  = s_red[1][e][0] + s_red[1][e][1] + s_red[1][e][2] + s_red[1][e][3];
        float mu  = s * (1.0f / H);
        float var = fmaxf(ss * (1.0f / H) - mu * mu, 0.0f);
        float inv = rsqrtf(var + EPSV);
        float out = s_cat[tid][e] + (acc2[e] - mu) * inv * gj + bj;  // residual
        int ei = e0 + e;
        ef[(size_t)ei * H + tid] = out;
        atomicAdd(&g_agg[(size_t)di[e] * H + tid], out);  // segment_sum by dst
    }
}

// ---------------------------------------------------------------------------
// Node update: cat=[agg, nf] (2H) -> Lin+SiLU -> Lin -> LN -> +nf (in place)
// ---------------------------------------------------------------------------
__global__ __launch_bounds__(128) void node_kernel(
    float* __restrict__ nfio,
    const float* __restrict__ W1, const float* __restrict__ b1,   // W1: [2H][H]
    const float* __restrict__ W2, const float* __restrict__ b2,   // W2: [H][H]
    const float* __restrict__ gg, const float* __restrict__ bb)
{
    __shared__ __align__(16) float s_cat[2 * H][NT];
    __shared__ __align__(16) float s_h[H][NT];
    __shared__ float s_red[2][NT][4];

    const int tid = threadIdx.x;
    const int n0  = blockIdx.x * NT;

#pragma unroll
    for (int e = 0; e < NT; e++) {
        int ni = n0 + e;
        s_cat[tid][e]     = g_agg[(size_t)ni * H + tid];
        s_cat[H + tid][e] = nfio[(size_t)ni * H + tid];
    }
    __syncthreads();

    float acc[NT];
    {
        float b = b1[tid];
#pragma unroll
        for (int e = 0; e < NT; e++) acc[e] = b;
    }
    const float* w1p = W1 + tid;
#pragma unroll 4
    for (int k = 0; k < 2 * H; k++) {
        float w = w1p[(size_t)k * H];
        fma8(acc, w, &s_cat[k][0]);
    }
#pragma unroll
    for (int e = 0; e < NT; e++) s_h[tid][e] = silu_f(acc[e]);
    __syncthreads();

    float acc2[NT];
    {
        float b = b2[tid];
#pragma unroll
        for (int e = 0; e < NT; e++) acc2[e] = b;
    }
    const float* w2p = W2 + tid;
#pragma unroll 4
    for (int k = 0; k < H; k++) {
        float w = w2p[(size_t)k * H];
        fma8(acc2, w, &s_h[k][0]);
    }

    float sum[NT], sq[NT];
#pragma unroll
    for (int e = 0; e < NT; e++) { sum[e] = acc2[e]; sq[e] = acc2[e] * acc2[e]; }
#pragma unroll
    for (int off = 16; off > 0; off >>= 1) {
#pragma unroll
        for (int e = 0; e < NT; e++) {
            sum[e] += __shfl_xor_sync(0xffffffffu, sum[e], off);
            sq[e]  += __shfl_xor_sync(0xffffffffu, sq[e],  off);
        }
    }
    const int warp = tid >> 5;
    if ((tid & 31) == 0) {
#pragma unroll
        for (int e = 0; e < NT; e++) { s_red[0][e][warp] = sum[e]; s_red[1][e][warp] = sq[e]; }
    }
    __syncthreads();

    const float gj = gg[tid], bj = bb[tid];
#pragma unroll
    for (int e = 0; e < NT; e++) {
        float s   = s_red[0][e][0] + s_red[0][e][1] + s_red[0][e][2] + s_red[0][e][3];
        float ss  = s_red[1][e][0] + s_red[1][e][1] + s_red[1][e][2] + s_red[1][e][3];
        float mu  = s * (1.0f / H);
        float var = fmaxf(ss * (1.0f / H) - mu * mu, 0.0f);
        float inv = rsqrtf(var + EPSV);
        float out = s_cat[H + tid][e] + (acc2[e] - mu) * inv * gj + bj; // residual
        nfio[(size_t)(n0 + e) * H + tid] = out;
    }
}

extern "C" void kernel_launch(void* const* d_in, const int* in_sizes, int n_in,
                              void* d_out, int out_size)
{
    const float* efeat = (const float*)d_in[0];
    const float* nfeat = (const float*)d_in[1];
    const int*   src   = (const int*)  d_in[2];
    const int*   dst   = (const int*)  d_in[3];
    const float* eW1   = (const float*)d_in[4];
    const float* eb1   = (const float*)d_in[5];
    const float* eW2   = (const float*)d_in[6];
    const float* eb2   = (const float*)d_in[7];
    const float* eg    = (const float*)d_in[8];
    const float* ebt   = (const float*)d_in[9];
    const float* nW1   = (const float*)d_in[10];
    const float* nb1   = (const float*)d_in[11];
    const float* nW2   = (const float*)d_in[12];
    const float* nb2   = (const float*)d_in[13];
    const float* ng    = (const float*)d_in[14];
    const float* nbt   = (const float*)d_in[15];

    const int E = in_sizes[0] / H;   // 160000
    const int N = in_sizes[1] / H;   // 10000

    // Output layout: ef [E*H] then nf [N*H]; operate in place on d_out.
    float* ef = (float*)d_out;
    float* nf = ef + (size_t)E * H;

    cudaMemcpyAsync(ef, efeat, sizeof(float) * (size_t)E * H, cudaMemcpyDeviceToDevice);
    cudaMemcpyAsync(nf, nfeat, sizeof(float) * (size_t)N * H, cudaMemcpyDeviceToDevice);

    const int aggTotal = N * H;
    for (int l = 0; l < LAYERS; l++) {
        zero_agg_kernel<<<(aggTotal + 255) / 256, 256>>>(aggTotal);
        edge_kernel<<<E / ET, 128>>>(
            ef, nf, src, dst,
            eW1 + (size_t)l * 3 * H * H, eb1 + (size_t)l * H,
            eW2 + (size_t)l * H * H,     eb2 + (size_t)l * H,
            eg  + (size_t)l * H,         ebt + (size_t)l * H);
        node_kernel<<<N / NT, 128>>>(
            nf,
            nW1 + (size_t)l * 2 * H * H, nb1 + (size_t)l * H,
            nW2 + (size_t)l * H * H,     nb2 + (size_t)l * H,
            ng  + (size_t)l * H,         nbt + (size_t)l * H);
    }
}